// round 6
// baseline (speedup 1.0000x reference)
#include <cuda_runtime.h>

#define T_TOK 500000
#define M_MEN 50000
#define B_BAG 5000
#define V_VOC 100000
#define D_DIM 256
#define K_TYP 100
#define K_PAD 128

// Scratch (no allocations allowed)
__device__ float g_men_emb[M_MEN * D_DIM];      // 51.2 MB
__device__ float g_sel[M_MEN];
__device__ float g_att[M_MEN];
__device__ float g_bag_emb[B_BAG * D_DIM];      // 5.12 MB
__device__ float g_Wt[D_DIM * K_PAD];           // 128 KB, W transposed d-major
__device__ int   g_type_idx[B_BAG];
__device__ int   g_men_type[M_MEN];             // per-mention selected type

// ---------------------------------------------------------------------------
// K0: per-bag argmax over typeTensor + scatter type to the bag's mentions.
// ---------------------------------------------------------------------------
__global__ void k0_argmax(const float* __restrict__ typeT,
                          const int*   __restrict__ scope,
                          int* __restrict__ tidx,
                          int* __restrict__ men_type) {
    int b    = blockIdx.x * (blockDim.x >> 5) + (threadIdx.x >> 5);
    int lane = threadIdx.x & 31;
    if (b >= B_BAG) return;
    float best = -INFINITY; int bi = K_TYP;
    for (int k = lane; k < K_TYP; k += 32) {
        float v = typeT[(size_t)b * K_TYP + k];
        if (v > best) { best = v; bi = k; }
    }
    #pragma unroll
    for (int off = 16; off; off >>= 1) {
        float ov = __shfl_xor_sync(0xffffffffu, best, off);
        int   oi = __shfl_xor_sync(0xffffffffu, bi,   off);
        if (ov > best || (ov == best && oi < bi)) { best = ov; bi = oi; }
    }
    if (lane == 0) tidx[b] = bi;
    int s = scope[b], e = scope[b + 1];
    for (int j = s + lane; j < e; j += 32) men_type[j] = bi;
}

// ---------------------------------------------------------------------------
// K0b: transpose W[100,256] -> g_Wt[256,128] (d-major, zero-padded k)
// ---------------------------------------------------------------------------
__global__ void k0b_transpose(const float* __restrict__ W, float* __restrict__ Wt) {
    int idx = blockIdx.x * blockDim.x + threadIdx.x;
    if (idx >= D_DIM * K_PAD) return;
    int d = idx >> 7, k = idx & 127;
    Wt[idx] = (k < K_TYP) ? W[(size_t)k * D_DIM + d] : 0.f;
}

// ---------------------------------------------------------------------------
// K1: TWO warps per mention (each owns 128 dims = 1 float4 per lane).
//     8-token unroll -> 8 independent 128B loads in flight per warp.
// ---------------------------------------------------------------------------
__global__ void k1_mention(const int*   __restrict__ feat,
                           const int*   __restrict__ offs,
                           const float* __restrict__ emb,
                           const float* __restrict__ lw,
                           const int*   __restrict__ men_type) {
    int wid  = threadIdx.x >> 5;               // 0..7
    int lane = threadIdx.x & 31;
    int gw   = blockIdx.x * 8 + wid;
    int m    = gw >> 1;
    int half = gw & 1;

    int start = offs[m];
    int end   = (m + 1 < M_MEN) ? offs[m + 1] : T_TOK;

    int col4 = half * 32 + lane;               // float4 index within row

    float4 acc = make_float4(0.f, 0.f, 0.f, 0.f);
    int p = start;
    for (; p + 8 <= end; p += 8) {
        int t0 = feat[p],     t1 = feat[p + 1];
        int t2 = feat[p + 2], t3 = feat[p + 3];
        int t4 = feat[p + 4], t5 = feat[p + 5];
        int t6 = feat[p + 6], t7 = feat[p + 7];
        float4 v0 = ((const float4*)(emb + (size_t)t0 * D_DIM))[col4];
        float4 v1 = ((const float4*)(emb + (size_t)t1 * D_DIM))[col4];
        float4 v2 = ((const float4*)(emb + (size_t)t2 * D_DIM))[col4];
        float4 v3 = ((const float4*)(emb + (size_t)t3 * D_DIM))[col4];
        float4 v4 = ((const float4*)(emb + (size_t)t4 * D_DIM))[col4];
        float4 v5 = ((const float4*)(emb + (size_t)t5 * D_DIM))[col4];
        float4 v6 = ((const float4*)(emb + (size_t)t6 * D_DIM))[col4];
        float4 v7 = ((const float4*)(emb + (size_t)t7 * D_DIM))[col4];
        acc.x += ((v0.x + v1.x) + (v2.x + v3.x)) + ((v4.x + v5.x) + (v6.x + v7.x));
        acc.y += ((v0.y + v1.y) + (v2.y + v3.y)) + ((v4.y + v5.y) + (v6.y + v7.y));
        acc.z += ((v0.z + v1.z) + (v2.z + v3.z)) + ((v4.z + v5.z) + (v6.z + v7.z));
        acc.w += ((v0.w + v1.w) + (v2.w + v3.w)) + ((v4.w + v5.w) + (v6.w + v7.w));
    }
    for (; p < end; p++) {
        int t0 = feat[p];
        float4 v0 = ((const float4*)(emb + (size_t)t0 * D_DIM))[col4];
        acc.x += v0.x; acc.y += v0.y; acc.z += v0.z; acc.w += v0.w;
    }
    float inv = 1.0f / (float)(end - start);
    acc.x *= inv; acc.y *= inv; acc.z *= inv; acc.w *= inv;

    __stcs(&((float4*)(g_men_emb + (size_t)m * D_DIM))[col4], acc);

    int t = men_type[m];
    float4 w = ((const float4*)(lw + (size_t)t * D_DIM))[col4];
    float d = acc.x * w.x + acc.y * w.y + acc.z * w.z + acc.w * w.w;
    #pragma unroll
    for (int off = 16; off; off >>= 1) d += __shfl_xor_sync(0xffffffffu, d, off);

    __shared__ float part[8];
    if (lane == 0) part[wid] = d;
    __syncthreads();
    if ((wid & 1) == 0 && lane == 0)
        g_sel[m] = part[wid] + part[wid + 1];
}

// ---------------------------------------------------------------------------
// K2: warp per bag — softmax over sel -> att (sel is tiny, L2-hot)
// ---------------------------------------------------------------------------
__global__ void k2_att(const int* __restrict__ scope) {
    int b    = blockIdx.x * (blockDim.x >> 5) + (threadIdx.x >> 5);
    int lane = threadIdx.x & 31;
    if (b >= B_BAG) return;
    int s = scope[b], e = scope[b + 1];

    float mx = -INFINITY;
    for (int m = s + lane; m < e; m += 32) mx = fmaxf(mx, g_sel[m]);
    #pragma unroll
    for (int off = 16; off; off >>= 1)
        mx = fmaxf(mx, __shfl_xor_sync(0xffffffffu, mx, off));

    float sum = 0.f;
    for (int m = s + lane; m < e; m += 32) sum += expf(g_sel[m] - mx);
    #pragma unroll
    for (int off = 16; off; off >>= 1)
        sum += __shfl_xor_sync(0xffffffffu, sum, off);
    float inv = 1.0f / sum;

    for (int m = s + lane; m < e; m += 32)
        g_att[m] = expf(g_sel[m] - mx) * inv;
}

// ---------------------------------------------------------------------------
// K3a: one 256-thread block per bag, NO syncs in main loop.
//      Thread (q=tid>>6, c=tid&63) accumulates float4 column c over mentions
//      m = s+q, s+q+4, ... (2-deep unroll -> 2 LDG.128 in flight).
//      att[m] is a warp-uniform broadcast load. One smem reduce at the end.
// ---------------------------------------------------------------------------
__global__ void k3a_bagemb(const int* __restrict__ scope,
                           float*     __restrict__ bag_emb) {
    int b   = blockIdx.x;
    int tid = threadIdx.x;
    int q   = tid >> 6;          // 0..3 mention phase
    int c   = tid & 63;          // float4 column
    int s = scope[b], e = scope[b + 1];

    float4 acc = make_float4(0.f, 0.f, 0.f, 0.f);
    int m = s + q;
    for (; m + 4 < e; m += 8) {
        float w0 = __ldg(&g_att[m]);
        float w1 = __ldg(&g_att[m + 4]);
        float4 v0 = __ldcs(&((const float4*)(g_men_emb + (size_t)m       * D_DIM))[c]);
        float4 v1 = __ldcs(&((const float4*)(g_men_emb + (size_t)(m + 4) * D_DIM))[c]);
        acc.x += w0 * v0.x + w1 * v1.x;
        acc.y += w0 * v0.y + w1 * v1.y;
        acc.z += w0 * v0.z + w1 * v1.z;
        acc.w += w0 * v0.w + w1 * v1.w;
    }
    if (m < e) {
        float w0 = __ldg(&g_att[m]);
        float4 v0 = __ldcs(&((const float4*)(g_men_emb + (size_t)m * D_DIM))[c]);
        acc.x += w0 * v0.x; acc.y += w0 * v0.y;
        acc.z += w0 * v0.z; acc.w += w0 * v0.w;
    }

    __shared__ float4 red[4][64];
    red[q][c] = acc;
    __syncthreads();
    if (tid < 64) {
        float4 r0 = red[0][tid], r1 = red[1][tid];
        float4 r2 = red[2][tid], r3 = red[3][tid];
        float4 r;
        r.x = (r0.x + r1.x) + (r2.x + r3.x);
        r.y = (r0.y + r1.y) + (r2.y + r3.y);
        r.z = (r0.z + r1.z) + (r2.z + r3.z);
        r.w = (r0.w + r1.w) + (r2.w + r3.w);
        ((float4*)(bag_emb + (size_t)b * D_DIM))[tid] = r;
    }
}

// ---------------------------------------------------------------------------
// K3b: GEMM out[5000,100] = bag_emb @ W^T using d-major g_Wt.
// ---------------------------------------------------------------------------
#define GEMM_BM 16
#define DSTAGE  64
__global__ void k3b_gemm(const float* __restrict__ A,
                         const float* __restrict__ Wt,
                         float*       __restrict__ out) {
    __shared__ float sW[DSTAGE][K_PAD];
    __shared__ float sA[DSTAGE][GEMM_BM + 4];
    int tid = threadIdx.x;                    // 128 threads
    int kt = tid & 31;
    int bt = tid >> 5;
    int bag0 = blockIdx.x * GEMM_BM;

    float4 acc[4];
    #pragma unroll
    for (int r = 0; r < 4; r++) acc[r] = make_float4(0.f, 0.f, 0.f, 0.f);

    for (int d0 = 0; d0 < D_DIM; d0 += DSTAGE) {
        #pragma unroll
        for (int i = 0; i < 16; i++) {
            int idx = tid + 128 * i;
            int d = idx >> 5, x = idx & 31;
            *(float4*)&sW[d][4 * x] =
                *(const float4*)(Wt + (size_t)(d0 + d) * K_PAD + 4 * x);
        }
        #pragma unroll
        for (int i = 0; i < 2; i++) {
            int idx = tid + 128 * i;
            int b = idx >> 4, x = idx & 15;
            int bag = bag0 + b;
            float4 v = (bag < B_BAG)
                ? *(const float4*)(A + (size_t)bag * D_DIM + d0 + 4 * x)
                : make_float4(0.f, 0.f, 0.f, 0.f);
            sA[4 * x + 0][b] = v.x; sA[4 * x + 1][b] = v.y;
            sA[4 * x + 2][b] = v.z; sA[4 * x + 3][b] = v.w;
        }
        __syncthreads();

        #pragma unroll 16
        for (int d = 0; d < DSTAGE; d++) {
            float4 wv = *(const float4*)&sW[d][4 * kt];
            float4 av = *(const float4*)&sA[d][4 * bt];
            acc[0].x += av.x * wv.x; acc[0].y += av.x * wv.y;
            acc[0].z += av.x * wv.z; acc[0].w += av.x * wv.w;
            acc[1].x += av.y * wv.x; acc[1].y += av.y * wv.y;
            acc[1].z += av.y * wv.z; acc[1].w += av.y * wv.w;
            acc[2].x += av.z * wv.x; acc[2].y += av.z * wv.y;
            acc[2].z += av.z * wv.z; acc[2].w += av.z * wv.w;
            acc[3].x += av.w * wv.x; acc[3].y += av.w * wv.y;
            acc[3].z += av.w * wv.z; acc[3].w += av.w * wv.w;
        }
        __syncthreads();
    }

    #pragma unroll
    for (int r = 0; r < 4; r++) {
        int bag = bag0 + 4 * bt + r;
        if (bag >= B_BAG) continue;
        int k = 4 * kt;
        if (k + 4 <= K_TYP) {
            *(float4*)(out + (size_t)bag * K_TYP + k) = acc[r];
        } else if (k < K_TYP) {
            float v[4] = {acc[r].x, acc[r].y, acc[r].z, acc[r].w};
            for (int j = 0; j < 4 && k + j < K_TYP; j++)
                out[(size_t)bag * K_TYP + k + j] = v[j];
        }
    }
}

// ---------------------------------------------------------------------------
extern "C" void kernel_launch(void* const* d_in, const int* in_sizes, int n_in,
                              void* d_out, int out_size) {
    const int*   feature_seq    = (const int*)  d_in[0];
    const int*   offset_seq     = (const int*)  d_in[1];
    const int*   scope          = (const int*)  d_in[2];
    const float* typeTensor     = (const float*)d_in[3];
    const float* word_embedding = (const float*)d_in[4];
    const float* linear_weight  = (const float*)d_in[5];
    float*       out            = (float*)d_out;

    int *tidx = nullptr, *mtype = nullptr;
    float *bagE = nullptr, *Wt = nullptr;
    cudaGetSymbolAddress((void**)&tidx,  g_type_idx);
    cudaGetSymbolAddress((void**)&mtype, g_men_type);
    cudaGetSymbolAddress((void**)&bagE,  g_bag_emb);
    cudaGetSymbolAddress((void**)&Wt,    g_Wt);

    k0_argmax<<<(B_BAG + 7) / 8, 256>>>(typeTensor, scope, tidx, mtype);
    k0b_transpose<<<(D_DIM * K_PAD + 255) / 256, 256>>>(linear_weight, Wt);
    k1_mention<<<(2 * M_MEN) / 8, 256>>>(feature_seq, offset_seq,
                                         word_embedding, linear_weight, mtype);
    k2_att<<<(B_BAG + 7) / 8, 256>>>(scope);
    k3a_bagemb<<<B_BAG, 256>>>(scope, bagE);
    k3b_gemm<<<(B_BAG + GEMM_BM - 1) / GEMM_BM, 128>>>(bagE, Wt, out);
}

// round 7
// speedup vs baseline: 1.2359x; 1.2359x over previous
#include <cuda_runtime.h>

#define T_TOK 500000
#define M_MEN 50000
#define B_BAG 5000
#define V_VOC 100000
#define D_DIM 256
#define K_TYP 100
#define K_PAD 128

// Scratch (no allocations allowed)
__device__ float g_men_emb[M_MEN * D_DIM];      // 51.2 MB
__device__ float g_sel_part[2 * M_MEN];         // per-half partial dots
__device__ float g_att[M_MEN];
__device__ float g_bag_emb[B_BAG * D_DIM];      // 5.12 MB
__device__ float g_Wt[D_DIM * K_PAD];           // 128 KB, W transposed d-major
__device__ int   g_men_type[M_MEN];             // per-mention selected type

#define K0_ARG_BLOCKS ((B_BAG + 7) / 8)
#define K0_TR_BLOCKS  ((D_DIM * K_PAD + 255) / 256)

// ---------------------------------------------------------------------------
// K0 (merged): blocks [0, K0_ARG_BLOCKS) do per-bag argmax + mention scatter;
//              blocks [K0_ARG_BLOCKS, +K0_TR_BLOCKS) transpose W -> Wt.
// ---------------------------------------------------------------------------
__global__ void k0_prep(const float* __restrict__ typeT,
                        const int*   __restrict__ scope,
                        const float* __restrict__ W,
                        int*   __restrict__ men_type,
                        float* __restrict__ Wt) {
    if (blockIdx.x >= K0_ARG_BLOCKS) {
        int idx = (blockIdx.x - K0_ARG_BLOCKS) * blockDim.x + threadIdx.x;
        if (idx < D_DIM * K_PAD) {
            int d = idx >> 7, k = idx & 127;
            Wt[idx] = (k < K_TYP) ? W[(size_t)k * D_DIM + d] : 0.f;
        }
        return;
    }
    int b    = blockIdx.x * (blockDim.x >> 5) + (threadIdx.x >> 5);
    int lane = threadIdx.x & 31;
    if (b >= B_BAG) return;
    float best = -INFINITY; int bi = K_TYP;
    for (int k = lane; k < K_TYP; k += 32) {
        float v = typeT[(size_t)b * K_TYP + k];
        if (v > best) { best = v; bi = k; }
    }
    #pragma unroll
    for (int off = 16; off; off >>= 1) {
        float ov = __shfl_xor_sync(0xffffffffu, best, off);
        int   oi = __shfl_xor_sync(0xffffffffu, bi,   off);
        if (ov > best || (ov == best && oi < bi)) { best = ov; bi = oi; }
    }
    int s = scope[b], e = scope[b + 1];
    for (int j = s + lane; j < e; j += 32) men_type[j] = bi;
}

// ---------------------------------------------------------------------------
// K1: TWO warps per mention (each owns 128 dims = 1 float4 per lane).
//     4-token unroll (measured sweet spot), __ldcg emb loads, NO block sync:
//     each half writes its partial dot to g_sel_part[gw].
// ---------------------------------------------------------------------------
__global__ void k1_mention(const int*   __restrict__ feat,
                           const int*   __restrict__ offs,
                           const float* __restrict__ emb,
                           const float* __restrict__ lw,
                           const int*   __restrict__ men_type) {
    int wid  = threadIdx.x >> 5;               // 0..7
    int lane = threadIdx.x & 31;
    int gw   = blockIdx.x * 8 + wid;
    int m    = gw >> 1;
    int half = gw & 1;

    int start = offs[m];
    int end   = (m + 1 < M_MEN) ? offs[m + 1] : T_TOK;

    int col4 = half * 32 + lane;               // float4 index within row

    float4 acc = make_float4(0.f, 0.f, 0.f, 0.f);
    int p = start;
    for (; p + 4 <= end; p += 4) {
        int t0 = feat[p],     t1 = feat[p + 1];
        int t2 = feat[p + 2], t3 = feat[p + 3];
        float4 v0 = __ldcg(&((const float4*)(emb + (size_t)t0 * D_DIM))[col4]);
        float4 v1 = __ldcg(&((const float4*)(emb + (size_t)t1 * D_DIM))[col4]);
        float4 v2 = __ldcg(&((const float4*)(emb + (size_t)t2 * D_DIM))[col4]);
        float4 v3 = __ldcg(&((const float4*)(emb + (size_t)t3 * D_DIM))[col4]);
        acc.x += (v0.x + v1.x) + (v2.x + v3.x);
        acc.y += (v0.y + v1.y) + (v2.y + v3.y);
        acc.z += (v0.z + v1.z) + (v2.z + v3.z);
        acc.w += (v0.w + v1.w) + (v2.w + v3.w);
    }
    for (; p < end; p++) {
        int t0 = feat[p];
        float4 v0 = __ldcg(&((const float4*)(emb + (size_t)t0 * D_DIM))[col4]);
        acc.x += v0.x; acc.y += v0.y; acc.z += v0.z; acc.w += v0.w;
    }
    float inv = 1.0f / (float)(end - start);
    acc.x *= inv; acc.y *= inv; acc.z *= inv; acc.w *= inv;

    __stcs(&((float4*)(g_men_emb + (size_t)m * D_DIM))[col4], acc);

    int t = men_type[m];
    float4 w = ((const float4*)(lw + (size_t)t * D_DIM))[col4];
    float d = acc.x * w.x + acc.y * w.y + acc.z * w.z + acc.w * w.w;
    #pragma unroll
    for (int off = 16; off; off >>= 1) d += __shfl_xor_sync(0xffffffffu, d, off);
    if (lane == 0) g_sel_part[gw] = d;
}

// ---------------------------------------------------------------------------
// K2: warp per bag — softmax over sel (= part[2m]+part[2m+1]) -> att
// ---------------------------------------------------------------------------
__global__ void k2_att(const int* __restrict__ scope) {
    int b    = blockIdx.x * (blockDim.x >> 5) + (threadIdx.x >> 5);
    int lane = threadIdx.x & 31;
    if (b >= B_BAG) return;
    int s = scope[b], e = scope[b + 1];

    float mx = -INFINITY;
    for (int m = s + lane; m < e; m += 32)
        mx = fmaxf(mx, g_sel_part[2 * m] + g_sel_part[2 * m + 1]);
    #pragma unroll
    for (int off = 16; off; off >>= 1)
        mx = fmaxf(mx, __shfl_xor_sync(0xffffffffu, mx, off));

    float sum = 0.f;
    for (int m = s + lane; m < e; m += 32)
        sum += expf(g_sel_part[2 * m] + g_sel_part[2 * m + 1] - mx);
    #pragma unroll
    for (int off = 16; off; off >>= 1)
        sum += __shfl_xor_sync(0xffffffffu, sum, off);
    float inv = 1.0f / sum;

    for (int m = s + lane; m < e; m += 32)
        g_att[m] = expf(g_sel_part[2 * m] + g_sel_part[2 * m + 1] - mx) * inv;
}

// ---------------------------------------------------------------------------
// K3a: one 128-thread block per bag, no syncs in main loop.
//      Thread (q=tid>>6 in {0,1}, c=tid&63) accumulates float4 column c over
//      mentions m = s+q, s+q+2, ... 2-deep unroll -> 2 LDG.128 in flight.
// ---------------------------------------------------------------------------
__global__ void k3a_bagemb(const int* __restrict__ scope,
                           float*     __restrict__ bag_emb) {
    int b   = blockIdx.x;
    int tid = threadIdx.x;       // 128
    int q   = tid >> 6;          // 0..1 mention phase
    int c   = tid & 63;          // float4 column
    int s = scope[b], e = scope[b + 1];

    float4 acc = make_float4(0.f, 0.f, 0.f, 0.f);
    int m = s + q;
    for (; m + 2 < e; m += 4) {
        float w0 = __ldg(&g_att[m]);
        float w1 = __ldg(&g_att[m + 2]);
        float4 v0 = __ldcs(&((const float4*)(g_men_emb + (size_t)m       * D_DIM))[c]);
        float4 v1 = __ldcs(&((const float4*)(g_men_emb + (size_t)(m + 2) * D_DIM))[c]);
        acc.x += w0 * v0.x + w1 * v1.x;
        acc.y += w0 * v0.y + w1 * v1.y;
        acc.z += w0 * v0.z + w1 * v1.z;
        acc.w += w0 * v0.w + w1 * v1.w;
    }
    if (m < e) {
        float w0 = __ldg(&g_att[m]);
        float4 v0 = __ldcs(&((const float4*)(g_men_emb + (size_t)m * D_DIM))[c]);
        acc.x += w0 * v0.x; acc.y += w0 * v0.y;
        acc.z += w0 * v0.z; acc.w += w0 * v0.w;
    }

    __shared__ float4 red[2][64];
    red[q][c] = acc;
    __syncthreads();
    if (tid < 64) {
        float4 r0 = red[0][tid], r1 = red[1][tid];
        float4 r;
        r.x = r0.x + r1.x; r.y = r0.y + r1.y;
        r.z = r0.z + r1.z; r.w = r0.w + r1.w;
        ((float4*)(bag_emb + (size_t)b * D_DIM))[tid] = r;
    }
}

// ---------------------------------------------------------------------------
// K3b: GEMM out[5000,100] = bag_emb @ W^T using d-major g_Wt.
// ---------------------------------------------------------------------------
#define GEMM_BM 16
#define DSTAGE  64
__global__ void k3b_gemm(const float* __restrict__ A,
                         const float* __restrict__ Wt,
                         float*       __restrict__ out) {
    __shared__ float sW[DSTAGE][K_PAD];
    __shared__ float sA[DSTAGE][GEMM_BM + 4];
    int tid = threadIdx.x;                    // 128 threads
    int kt = tid & 31;
    int bt = tid >> 5;
    int bag0 = blockIdx.x * GEMM_BM;

    float4 acc[4];
    #pragma unroll
    for (int r = 0; r < 4; r++) acc[r] = make_float4(0.f, 0.f, 0.f, 0.f);

    for (int d0 = 0; d0 < D_DIM; d0 += DSTAGE) {
        #pragma unroll
        for (int i = 0; i < 16; i++) {
            int idx = tid + 128 * i;
            int d = idx >> 5, x = idx & 31;
            *(float4*)&sW[d][4 * x] =
                *(const float4*)(Wt + (size_t)(d0 + d) * K_PAD + 4 * x);
        }
        #pragma unroll
        for (int i = 0; i < 2; i++) {
            int idx = tid + 128 * i;
            int b = idx >> 4, x = idx & 15;
            int bag = bag0 + b;
            float4 v = (bag < B_BAG)
                ? *(const float4*)(A + (size_t)bag * D_DIM + d0 + 4 * x)
                : make_float4(0.f, 0.f, 0.f, 0.f);
            sA[4 * x + 0][b] = v.x; sA[4 * x + 1][b] = v.y;
            sA[4 * x + 2][b] = v.z; sA[4 * x + 3][b] = v.w;
        }
        __syncthreads();

        #pragma unroll 16
        for (int d = 0; d < DSTAGE; d++) {
            float4 wv = *(const float4*)&sW[d][4 * kt];
            float4 av = *(const float4*)&sA[d][4 * bt];
            acc[0].x += av.x * wv.x; acc[0].y += av.x * wv.y;
            acc[0].z += av.x * wv.z; acc[0].w += av.x * wv.w;
            acc[1].x += av.y * wv.x; acc[1].y += av.y * wv.y;
            acc[1].z += av.y * wv.z; acc[1].w += av.y * wv.w;
            acc[2].x += av.z * wv.x; acc[2].y += av.z * wv.y;
            acc[2].z += av.z * wv.z; acc[2].w += av.z * wv.w;
            acc[3].x += av.w * wv.x; acc[3].y += av.w * wv.y;
            acc[3].z += av.w * wv.z; acc[3].w += av.w * wv.w;
        }
        __syncthreads();
    }

    #pragma unroll
    for (int r = 0; r < 4; r++) {
        int bag = bag0 + 4 * bt + r;
        if (bag >= B_BAG) continue;
        int k = 4 * kt;
        if (k + 4 <= K_TYP) {
            *(float4*)(out + (size_t)bag * K_TYP + k) = acc[r];
        } else if (k < K_TYP) {
            float v[4] = {acc[r].x, acc[r].y, acc[r].z, acc[r].w};
            for (int j = 0; j < 4 && k + j < K_TYP; j++)
                out[(size_t)bag * K_TYP + k + j] = v[j];
        }
    }
}

// ---------------------------------------------------------------------------
extern "C" void kernel_launch(void* const* d_in, const int* in_sizes, int n_in,
                              void* d_out, int out_size) {
    const int*   feature_seq    = (const int*)  d_in[0];
    const int*   offset_seq     = (const int*)  d_in[1];
    const int*   scope          = (const int*)  d_in[2];
    const float* typeTensor     = (const float*)d_in[3];
    const float* word_embedding = (const float*)d_in[4];
    const float* linear_weight  = (const float*)d_in[5];
    float*       out            = (float*)d_out;

    int*   mtype = nullptr;
    float *bagE = nullptr, *Wt = nullptr;
    cudaGetSymbolAddress((void**)&mtype, g_men_type);
    cudaGetSymbolAddress((void**)&bagE,  g_bag_emb);
    cudaGetSymbolAddress((void**)&Wt,    g_Wt);

    k0_prep<<<K0_ARG_BLOCKS + K0_TR_BLOCKS, 256>>>(typeTensor, scope,
                                                   linear_weight, mtype, Wt);
    k1_mention<<<(2 * M_MEN) / 8, 256>>>(feature_seq, offset_seq,
                                         word_embedding, linear_weight, mtype);
    k2_att<<<(B_BAG + 7) / 8, 256>>>(scope);
    k3a_bagemb<<<B_BAG, 128>>>(scope, bagE);
    k3b_gemm<<<(B_BAG + GEMM_BM - 1) / GEMM_BM, 128>>>(bagE, Wt, out);
}

// round 8
// speedup vs baseline: 1.3127x; 1.0622x over previous
#include <cuda_runtime.h>
#include <cuda_fp16.h>

#define T_TOK 500000
#define M_MEN 50000
#define B_BAG 5000
#define V_VOC 100000
#define D_DIM 256
#define K_TYP 100
#define K_PAD 128

// Scratch (no allocations allowed)
__device__ __half g_men_emb[M_MEN * D_DIM];     // 25.6 MB (fp16 intermediate)
__device__ float  g_sel_part[2 * M_MEN];        // per-half partial dots (fp32)
__device__ float  g_att[M_MEN];
__device__ float  g_bag_emb[B_BAG * D_DIM];     // 5.12 MB
__device__ float  g_Wt[D_DIM * K_PAD];          // 128 KB, W transposed d-major
__device__ int    g_men_type[M_MEN];            // per-mention selected type

#define K0_ARG_BLOCKS ((B_BAG + 7) / 8)
#define K0_TR_BLOCKS  ((D_DIM * K_PAD + 255) / 256)

// ---------------------------------------------------------------------------
// K0 (merged): blocks [0, K0_ARG_BLOCKS) do per-bag argmax + mention scatter;
//              blocks [K0_ARG_BLOCKS, +K0_TR_BLOCKS) transpose W -> Wt.
// ---------------------------------------------------------------------------
__global__ void k0_prep(const float* __restrict__ typeT,
                        const int*   __restrict__ scope,
                        const float* __restrict__ W,
                        int*   __restrict__ men_type,
                        float* __restrict__ Wt) {
    if (blockIdx.x >= K0_ARG_BLOCKS) {
        int idx = (blockIdx.x - K0_ARG_BLOCKS) * blockDim.x + threadIdx.x;
        if (idx < D_DIM * K_PAD) {
            int d = idx >> 7, k = idx & 127;
            Wt[idx] = (k < K_TYP) ? W[(size_t)k * D_DIM + d] : 0.f;
        }
        return;
    }
    int b    = blockIdx.x * (blockDim.x >> 5) + (threadIdx.x >> 5);
    int lane = threadIdx.x & 31;
    if (b >= B_BAG) return;
    float best = -INFINITY; int bi = K_TYP;
    for (int k = lane; k < K_TYP; k += 32) {
        float v = typeT[(size_t)b * K_TYP + k];
        if (v > best) { best = v; bi = k; }
    }
    #pragma unroll
    for (int off = 16; off; off >>= 1) {
        float ov = __shfl_xor_sync(0xffffffffu, best, off);
        int   oi = __shfl_xor_sync(0xffffffffu, bi,   off);
        if (ov > best || (ov == best && oi < bi)) { best = ov; bi = oi; }
    }
    int s = scope[b], e = scope[b + 1];
    for (int j = s + lane; j < e; j += 32) men_type[j] = bi;
}

// ---------------------------------------------------------------------------
// K1: TWO warps per mention (each owns 128 dims = 1 float4 per lane).
//     4-token unroll, __ldcg emb loads, no block sync.
//     men_emb stored as fp16 (4 halves = 8B per lane, evict-first);
//     sel partial dot computed from the fp32 accumulator.
// ---------------------------------------------------------------------------
__global__ void k1_mention(const int*   __restrict__ feat,
                           const int*   __restrict__ offs,
                           const float* __restrict__ emb,
                           const float* __restrict__ lw,
                           const int*   __restrict__ men_type) {
    int wid  = threadIdx.x >> 5;               // 0..7
    int lane = threadIdx.x & 31;
    int gw   = blockIdx.x * 8 + wid;
    int m    = gw >> 1;
    int half = gw & 1;

    int start = offs[m];
    int end   = (m + 1 < M_MEN) ? offs[m + 1] : T_TOK;

    int col4 = half * 32 + lane;               // float4 index within row

    float4 acc = make_float4(0.f, 0.f, 0.f, 0.f);
    int p = start;
    for (; p + 4 <= end; p += 4) {
        int t0 = feat[p],     t1 = feat[p + 1];
        int t2 = feat[p + 2], t3 = feat[p + 3];
        float4 v0 = __ldcg(&((const float4*)(emb + (size_t)t0 * D_DIM))[col4]);
        float4 v1 = __ldcg(&((const float4*)(emb + (size_t)t1 * D_DIM))[col4]);
        float4 v2 = __ldcg(&((const float4*)(emb + (size_t)t2 * D_DIM))[col4]);
        float4 v3 = __ldcg(&((const float4*)(emb + (size_t)t3 * D_DIM))[col4]);
        acc.x += (v0.x + v1.x) + (v2.x + v3.x);
        acc.y += (v0.y + v1.y) + (v2.y + v3.y);
        acc.z += (v0.z + v1.z) + (v2.z + v3.z);
        acc.w += (v0.w + v1.w) + (v2.w + v3.w);
    }
    for (; p < end; p++) {
        int t0 = feat[p];
        float4 v0 = __ldcg(&((const float4*)(emb + (size_t)t0 * D_DIM))[col4]);
        acc.x += v0.x; acc.y += v0.y; acc.z += v0.z; acc.w += v0.w;
    }
    float inv = 1.0f / (float)(end - start);
    acc.x *= inv; acc.y *= inv; acc.z *= inv; acc.w *= inv;

    // fp16 pack (4 halves = 8 bytes), evict-first store
    __half2 h01 = __floats2half2_rn(acc.x, acc.y);
    __half2 h23 = __floats2half2_rn(acc.z, acc.w);
    uint2 packed;
    packed.x = *(const unsigned int*)&h01;
    packed.y = *(const unsigned int*)&h23;
    __stcs(&((uint2*)g_men_emb)[(size_t)m * 64 + col4], packed);

    int t = men_type[m];
    float4 w = ((const float4*)(lw + (size_t)t * D_DIM))[col4];
    float d = acc.x * w.x + acc.y * w.y + acc.z * w.z + acc.w * w.w;
    #pragma unroll
    for (int off = 16; off; off >>= 1) d += __shfl_xor_sync(0xffffffffu, d, off);
    if (lane == 0) g_sel_part[gw] = d;
}

// ---------------------------------------------------------------------------
// K2: warp per bag — softmax over sel (= part[2m]+part[2m+1]) -> att
// ---------------------------------------------------------------------------
__global__ void k2_att(const int* __restrict__ scope) {
    int b    = blockIdx.x * (blockDim.x >> 5) + (threadIdx.x >> 5);
    int lane = threadIdx.x & 31;
    if (b >= B_BAG) return;
    int s = scope[b], e = scope[b + 1];

    float mx = -INFINITY;
    for (int m = s + lane; m < e; m += 32)
        mx = fmaxf(mx, g_sel_part[2 * m] + g_sel_part[2 * m + 1]);
    #pragma unroll
    for (int off = 16; off; off >>= 1)
        mx = fmaxf(mx, __shfl_xor_sync(0xffffffffu, mx, off));

    float sum = 0.f;
    for (int m = s + lane; m < e; m += 32)
        sum += expf(g_sel_part[2 * m] + g_sel_part[2 * m + 1] - mx);
    #pragma unroll
    for (int off = 16; off; off >>= 1)
        sum += __shfl_xor_sync(0xffffffffu, sum, off);
    float inv = 1.0f / sum;

    for (int m = s + lane; m < e; m += 32)
        g_att[m] = expf(g_sel_part[2 * m] + g_sel_part[2 * m + 1] - mx) * inv;
}

// ---------------------------------------------------------------------------
// K3a: one 128-thread block per bag, no syncs in main loop.
//      Thread (q=tid>>6 in {0,1}, c=tid&63) accumulates fp16 column group c
//      (4 halves = 8B) over mentions m = s+q, s+q+2, ...; 2 loads in flight.
// ---------------------------------------------------------------------------
__global__ void k3a_bagemb(const int* __restrict__ scope,
                           float*     __restrict__ bag_emb) {
    int b   = blockIdx.x;
    int tid = threadIdx.x;       // 128
    int q   = tid >> 6;          // 0..1 mention phase
    int c   = tid & 63;          // uint2 (4-half) column group
    int s = scope[b], e = scope[b + 1];

    const uint2* me = (const uint2*)g_men_emb;

    float4 acc = make_float4(0.f, 0.f, 0.f, 0.f);
    int m = s + q;
    for (; m + 2 < e; m += 4) {
        float w0 = __ldg(&g_att[m]);
        float w1 = __ldg(&g_att[m + 2]);
        uint2 u0 = __ldcs(&me[(size_t)m       * 64 + c]);
        uint2 u1 = __ldcs(&me[(size_t)(m + 2) * 64 + c]);
        float2 a01 = __half22float2(*(const __half2*)&u0.x);
        float2 a23 = __half22float2(*(const __half2*)&u0.y);
        float2 b01 = __half22float2(*(const __half2*)&u1.x);
        float2 b23 = __half22float2(*(const __half2*)&u1.y);
        acc.x += w0 * a01.x + w1 * b01.x;
        acc.y += w0 * a01.y + w1 * b01.y;
        acc.z += w0 * a23.x + w1 * b23.x;
        acc.w += w0 * a23.y + w1 * b23.y;
    }
    if (m < e) {
        float w0 = __ldg(&g_att[m]);
        uint2 u0 = __ldcs(&me[(size_t)m * 64 + c]);
        float2 a01 = __half22float2(*(const __half2*)&u0.x);
        float2 a23 = __half22float2(*(const __half2*)&u0.y);
        acc.x += w0 * a01.x; acc.y += w0 * a01.y;
        acc.z += w0 * a23.x; acc.w += w0 * a23.y;
    }

    __shared__ float4 red[2][64];
    red[q][c] = acc;
    __syncthreads();
    if (tid < 64) {
        float4 r0 = red[0][tid], r1 = red[1][tid];
        float4 r;
        r.x = r0.x + r1.x; r.y = r0.y + r1.y;
        r.z = r0.z + r1.z; r.w = r0.w + r1.w;
        ((float4*)(bag_emb + (size_t)b * D_DIM))[tid] = r;
    }
}

// ---------------------------------------------------------------------------
// K3b: GEMM out[5000,100] = bag_emb @ W^T using d-major g_Wt.
// ---------------------------------------------------------------------------
#define GEMM_BM 16
#define DSTAGE  64
__global__ void k3b_gemm(const float* __restrict__ A,
                         const float* __restrict__ Wt,
                         float*       __restrict__ out) {
    __shared__ float sW[DSTAGE][K_PAD];
    __shared__ float sA[DSTAGE][GEMM_BM + 4];
    int tid = threadIdx.x;                    // 128 threads
    int kt = tid & 31;
    int bt = tid >> 5;
    int bag0 = blockIdx.x * GEMM_BM;

    float4 acc[4];
    #pragma unroll
    for (int r = 0; r < 4; r++) acc[r] = make_float4(0.f, 0.f, 0.f, 0.f);

    for (int d0 = 0; d0 < D_DIM; d0 += DSTAGE) {
        #pragma unroll
        for (int i = 0; i < 16; i++) {
            int idx = tid + 128 * i;
            int d = idx >> 5, x = idx & 31;
            *(float4*)&sW[d][4 * x] =
                *(const float4*)(Wt + (size_t)(d0 + d) * K_PAD + 4 * x);
        }
        #pragma unroll
        for (int i = 0; i < 2; i++) {
            int idx = tid + 128 * i;
            int b = idx >> 4, x = idx & 15;
            int bag = bag0 + b;
            float4 v = (bag < B_BAG)
                ? *(const float4*)(A + (size_t)bag * D_DIM + d0 + 4 * x)
                : make_float4(0.f, 0.f, 0.f, 0.f);
            sA[4 * x + 0][b] = v.x; sA[4 * x + 1][b] = v.y;
            sA[4 * x + 2][b] = v.z; sA[4 * x + 3][b] = v.w;
        }
        __syncthreads();

        #pragma unroll 16
        for (int d = 0; d < DSTAGE; d++) {
            float4 wv = *(const float4*)&sW[d][4 * kt];
            float4 av = *(const float4*)&sA[d][4 * bt];
            acc[0].x += av.x * wv.x; acc[0].y += av.x * wv.y;
            acc[0].z += av.x * wv.z; acc[0].w += av.x * wv.w;
            acc[1].x += av.y * wv.x; acc[1].y += av.y * wv.y;
            acc[1].z += av.y * wv.z; acc[1].w += av.y * wv.w;
            acc[2].x += av.z * wv.x; acc[2].y += av.z * wv.y;
            acc[2].z += av.z * wv.z; acc[2].w += av.z * wv.w;
            acc[3].x += av.w * wv.x; acc[3].y += av.w * wv.y;
            acc[3].z += av.w * wv.z; acc[3].w += av.w * wv.w;
        }
        __syncthreads();
    }

    #pragma unroll
    for (int r = 0; r < 4; r++) {
        int bag = bag0 + 4 * bt + r;
        if (bag >= B_BAG) continue;
        int k = 4 * kt;
        if (k + 4 <= K_TYP) {
            *(float4*)(out + (size_t)bag * K_TYP + k) = acc[r];
        } else if (k < K_TYP) {
            float v[4] = {acc[r].x, acc[r].y, acc[r].z, acc[r].w};
            for (int j = 0; j < 4 && k + j < K_TYP; j++)
                out[(size_t)bag * K_TYP + k + j] = v[j];
        }
    }
}

// ---------------------------------------------------------------------------
extern "C" void kernel_launch(void* const* d_in, const int* in_sizes, int n_in,
                              void* d_out, int out_size) {
    const int*   feature_seq    = (const int*)  d_in[0];
    const int*   offset_seq     = (const int*)  d_in[1];
    const int*   scope          = (const int*)  d_in[2];
    const float* typeTensor     = (const float*)d_in[3];
    const float* word_embedding = (const float*)d_in[4];
    const float* linear_weight  = (const float*)d_in[5];
    float*       out            = (float*)d_out;

    int*   mtype = nullptr;
    float *bagE = nullptr, *Wt = nullptr;
    cudaGetSymbolAddress((void**)&mtype, g_men_type);
    cudaGetSymbolAddress((void**)&bagE,  g_bag_emb);
    cudaGetSymbolAddress((void**)&Wt,    g_Wt);

    k0_prep<<<K0_ARG_BLOCKS + K0_TR_BLOCKS, 256>>>(typeTensor, scope,
                                                   linear_weight, mtype, Wt);
    k1_mention<<<(2 * M_MEN) / 8, 256>>>(feature_seq, offset_seq,
                                         word_embedding, linear_weight, mtype);
    k2_att<<<(B_BAG + 7) / 8, 256>>>(scope);
    k3a_bagemb<<<B_BAG, 128>>>(scope, bagE);
    k3b_gemm<<<(B_BAG + GEMM_BM - 1) / GEMM_BM, 128>>>(bagE, Wt, out);
}